// round 3
// baseline (speedup 1.0000x reference)
#include <cuda_runtime.h>
#include <cstdint>

#define NN 8192
#define DIN 256
#define DOUT 32
#define NPOOL 128

// ---------------- scratch (device globals) ----------------
__device__ float    g_support[NN * DOUT];
__device__ float    g_logits[NN * DOUT];
__device__ unsigned g_colmax_bits[DOUT];
__device__ float    g_sumpart[NPOOL * DOUT];
__device__ float    g_part[NPOOL * DOUT * DIN];

// ---------------- packed fp32x2 (FFMA2) helpers ----------------
__device__ __forceinline__ unsigned long long pack2(float x) {
    unsigned long long r;
    asm("mov.b64 %0, {%1, %1};" : "=l"(r) : "f"(x));
    return r;
}
__device__ __forceinline__ unsigned long long ffma2(unsigned long long a,
                                                    unsigned long long b,
                                                    unsigned long long c) {
    unsigned long long d;
    asm("fma.rn.f32x2 %0, %1, %2, %3;" : "=l"(d) : "l"(a), "l"(b), "l"(c));
    return d;
}
__device__ __forceinline__ float2 unpack2(unsigned long long v) {
    float2 f;
    asm("mov.b64 {%0, %1}, %2;" : "=f"(f.x), "=f"(f.y) : "l"(v));
    return f;
}

// monotone float<->uint order-preserving key
__device__ __forceinline__ unsigned fkey(float f) {
    int b = __float_as_int(f);
    return (unsigned)(b ^ ((b >> 31) | 0x80000000));
}
__device__ __forceinline__ float funkey(unsigned u) {
    int b = (u & 0x80000000u) ? (int)(u ^ 0x80000000u) : ~(int)u;
    return __int_as_float(b);
}

// ---------------------------------------------------------------------------
// C[M x 32] = A[M x K] @ S[K x 32]  (round-1 tiling: 64 rows/CTA, 2 rows/lane,
// 8 warps k-split, chunk=32k, inner loop 32 FFMA2 : 10 LDS)
// NEW: launch_bounds(256,2) -> 2 CTAs/SM (194KB smem) -> 4 warps/SMSP.
// Optional epilogue: per-column max via atomicMax on monotone keys
// (order-independent -> deterministic).
// ---------------------------------------------------------------------------
#define ABUF_STRIDE (32 * 65)           // floats per warp
#define SBUF_BASE   (8 * ABUF_STRIDE)
#define GEMM_SMEM_BYTES ((SBUF_BASE + 8 * 32 * 32) * 4)   // 99328 B

__global__ void __launch_bounds__(256, 2)
gemm_n32_kernel(const float* __restrict__ A, const float* __restrict__ S,
                float* __restrict__ C, int K, int do_max, int do_init)
{
    extern __shared__ float smem[];
    __shared__ unsigned smax[DOUT];
    const int t  = threadIdx.x;
    const int w  = t >> 5;
    const int l  = t & 31;
    const int rb = blockIdx.x * 64;

    if (do_init && blockIdx.x == 0 && t < DOUT) g_colmax_bits[t] = 0u;
    if (do_max && t < DOUT) smax[t] = 0u;

    float* a_buf = smem + w * ABUF_STRIDE;
    float* s_buf = smem + SBUF_BASE + w * (32 * 32);

    const int kslice = K >> 3;
    const int nchunk = kslice >> 5;
    const int k0 = w * kslice;

    unsigned long long acc0[16], acc1[16];
#pragma unroll
    for (int i = 0; i < 16; i++) { acc0[i] = 0ull; acc1[i] = 0ull; }

    for (int ch = 0; ch < nchunk; ch++) {
        const int kc = k0 + ch * 32;
        __syncwarp();
        // stage A: 64 rows x 32 k -> transposed [k][row], pad 65 (conflict-free)
#pragma unroll
        for (int j = 0; j < 16; j++) {
            int f   = j * 32 + l;
            int row = f >> 3;
            int k4  = (f & 7) << 2;
            float4 v = *reinterpret_cast<const float4*>(
                A + (size_t)(rb + row) * K + kc + k4);
            a_buf[(k4 + 0) * 65 + row] = v.x;
            a_buf[(k4 + 1) * 65 + row] = v.y;
            a_buf[(k4 + 2) * 65 + row] = v.z;
            a_buf[(k4 + 3) * 65 + row] = v.w;
        }
        // stage S: 32 k x 32 c, contiguous
#pragma unroll
        for (int j = 0; j < 8; j++) {
            int f = j * 32 + l;
            *reinterpret_cast<float4*>(s_buf + f * 4) =
                *reinterpret_cast<const float4*>(S + (size_t)kc * 32 + f * 4);
        }
        __syncwarp();
        // compute: lane owns rows (l, l+32) x all 32 cols
#pragma unroll 4
        for (int k = 0; k < 32; k++) {
            unsigned long long a0 = pack2(a_buf[k * 65 + l]);
            unsigned long long a1 = pack2(a_buf[k * 65 + l + 32]);
            const ulonglong2* s2 =
                reinterpret_cast<const ulonglong2*>(s_buf + k * 32);
#pragma unroll
            for (int c = 0; c < 8; c++) {
                ulonglong2 sv = s2[c];                 // LDS.128 broadcast
                acc0[2 * c]     = ffma2(a0, sv.x, acc0[2 * c]);
                acc0[2 * c + 1] = ffma2(a0, sv.y, acc0[2 * c + 1]);
                acc1[2 * c]     = ffma2(a1, sv.x, acc1[2 * c]);
                acc1[2 * c + 1] = ffma2(a1, sv.y, acc1[2 * c + 1]);
            }
        }
    }

    // ---- cross-warp fixed-order reduce (deterministic) ----
    __syncthreads();
    float* red = smem;  // overlay [8][64][33] = 67584 B
#pragma unroll
    for (int c = 0; c < 16; c++) {
        float2 v0 = unpack2(acc0[c]);
        float2 v1 = unpack2(acc1[c]);
        red[(w * 64 + l) * 33 + 2 * c]          = v0.x;
        red[(w * 64 + l) * 33 + 2 * c + 1]      = v0.y;
        red[(w * 64 + l + 32) * 33 + 2 * c]     = v1.x;
        red[(w * 64 + l + 32) * 33 + 2 * c + 1] = v1.y;
    }
    __syncthreads();
    {
        int row = t >> 2;
        int c0  = (t & 3) * 8;
        float r[8];
#pragma unroll
        for (int i = 0; i < 8; i++) r[i] = 0.0f;
#pragma unroll
        for (int ww = 0; ww < 8; ww++) {
            const float* p = red + (ww * 64 + row) * 33 + c0;
#pragma unroll
            for (int i = 0; i < 8; i++) r[i] += p[i];
        }
        float4* dst = reinterpret_cast<float4*>(C + (size_t)(rb + row) * 32 + c0);
        dst[0] = make_float4(r[0], r[1], r[2], r[3]);
        dst[1] = make_float4(r[4], r[5], r[6], r[7]);
        if (do_max) {
#pragma unroll
            for (int i = 0; i < 8; i++)
                atomicMax(&smax[c0 + i], fkey(r[i]));
        }
    }
    if (do_max) {
        __syncthreads();
        if (t < DOUT) atomicMax(&g_colmax_bits[t], smax[t]);
    }
}

// ---------------------------------------------------------------------------
// Partial exp-sums per 64-row block (coalesced reads, fixed-order reduce)
// ---------------------------------------------------------------------------
__global__ void __launch_bounds__(256, 2)
expsum_kernel()
{
    __shared__ float sred[64 * 33];
    __shared__ float cmax[DOUT];
    const int t  = threadIdx.x;
    const int rb = blockIdx.x * 64;

    if (t < DOUT) cmax[t] = funkey(g_colmax_bits[t]);
    __syncthreads();

    const int row = t >> 2;
    const int c0  = (t & 3) * 8;
#pragma unroll
    for (int h = 0; h < 2; h++) {
        float4 v = *reinterpret_cast<const float4*>(
            g_logits + (size_t)(rb + row) * DOUT + c0 + h * 4);
        sred[row * 33 + c0 + h * 4 + 0] = __expf(v.x - cmax[c0 + h * 4 + 0]);
        sred[row * 33 + c0 + h * 4 + 1] = __expf(v.y - cmax[c0 + h * 4 + 1]);
        sred[row * 33 + c0 + h * 4 + 2] = __expf(v.z - cmax[c0 + h * 4 + 2]);
        sred[row * 33 + c0 + h * 4 + 3] = __expf(v.w - cmax[c0 + h * 4 + 3]);
    }
    __syncthreads();
    if (t < DOUT) {
        float s = 0.f;
#pragma unroll 8
        for (int r = 0; r < 64; r++) s += sred[r * 33 + t];
        g_sumpart[blockIdx.x * DOUT + t] = s;
    }
}

// ---------------------------------------------------------------------------
// UNNORMALIZED pooling partials: part[blk][c][d] = sum_i exp(lg-max) * X[i][d]
// (normalization deferred to reduce_out -> no colinv kernel, no extra dep)
// 128 CTAs x 64 rows; thread t = feature d; row loop unrolled x8 (MLP 8).
// ---------------------------------------------------------------------------
__global__ void __launch_bounds__(256, 2)
pool_kernel(const float* __restrict__ X)
{
    __shared__ float wsm[64 * DOUT];
    __shared__ float cmax[DOUT];
    const int t  = threadIdx.x;
    const int rb = blockIdx.x * 64;

    if (t < DOUT) cmax[t] = funkey(g_colmax_bits[t]);
    __syncthreads();

#pragma unroll
    for (int q = 0; q < 8; q++) {
        int idx = t * 8 + q;
        int il  = idx >> 5;
        int c   = idx & 31;
        float lg = g_logits[(size_t)(rb + il) * DOUT + c];
        wsm[idx] = __expf(lg - cmax[c]);
    }
    __syncthreads();

    unsigned long long acc[16];
#pragma unroll
    for (int i = 0; i < 16; i++) acc[i] = 0ull;

    for (int g = 0; g < 8; g++) {
        float xv[8];
#pragma unroll
        for (int q = 0; q < 8; q++)
            xv[q] = X[(size_t)(rb + g * 8 + q) * DIN + t];   // 8 indep LDGs
#pragma unroll
        for (int q = 0; q < 8; q++) {
            unsigned long long xp = pack2(xv[q]);
            const ulonglong2* wv =
                reinterpret_cast<const ulonglong2*>(wsm + (g * 8 + q) * DOUT);
#pragma unroll
            for (int c = 0; c < 8; c++) {
                ulonglong2 sv = wv[c];
                acc[2 * c]     = ffma2(xp, sv.x, acc[2 * c]);
                acc[2 * c + 1] = ffma2(xp, sv.y, acc[2 * c + 1]);
            }
        }
    }

    float* pp = g_part + (size_t)blockIdx.x * (DOUT * DIN);
#pragma unroll
    for (int c = 0; c < 16; c++) {
        float2 v = unpack2(acc[c]);
        pp[(2 * c) * DIN + t]     = v.x;
        pp[(2 * c + 1) * DIN + t] = v.y;
    }
}

// ---------------------------------------------------------------------------
// Final reduce + normalize: out[c][d] = (1/sum_exp[c]) * sum_b part[b][c][d]
// ---------------------------------------------------------------------------
__global__ void reduce_out_kernel(float* __restrict__ out)
{
    __shared__ float sred[128];
    const int c = blockIdx.x;     // 32
    const int t = threadIdx.x;    // 256

    if (t < 128) sred[t] = g_sumpart[t * DOUT + c];
    __syncthreads();
    for (int s = 64; s > 0; s >>= 1) {
        if (t < s) sred[t] += sred[t + s];
        __syncthreads();
    }
    const float inv = 1.0f / sred[0];

    float s = 0.0f;
#pragma unroll 8
    for (int b = 0; b < NPOOL; b++)
        s += g_part[(size_t)b * (DOUT * DIN) + c * DIN + t];
    out[c * DIN + t] = s * inv;
}

// ---------------------------------------------------------------------------
extern "C" void kernel_launch(void* const* d_in, const int* in_sizes, int n_in,
                              void* d_out, int out_size)
{
    const float* X = (const float*)d_in[0];   // main_feat [8192,256]
    const float* A = (const float*)d_in[1];   // main_adj  [8192,8192]
    const float* W = (const float*)d_in[2];   // W         [256,32]
    // d_in[3] = b: per-column constant -> softmax over axis 0 invariant -> dropped
    float* out = (float*)d_out;

    float *sup, *logits;
    cudaGetSymbolAddress((void**)&sup, g_support);
    cudaGetSymbolAddress((void**)&logits, g_logits);

    cudaFuncSetAttribute(gemm_n32_kernel,
                         cudaFuncAttributeMaxDynamicSharedMemorySize,
                         GEMM_SMEM_BYTES);

    // 1) support = X @ W  (+ zero colmax from CTA 0)
    gemm_n32_kernel<<<NN / 64, 256, GEMM_SMEM_BYTES>>>(X, W, sup, DIN, 0, 1);
    // 2) logits = A @ support  (+ fused per-column max epilogue)
    gemm_n32_kernel<<<NN / 64, 256, GEMM_SMEM_BYTES>>>(A, sup, logits, NN, 1, 0);
    // 3) partial exp-sums
    expsum_kernel<<<NPOOL, 256>>>();
    // 4) unnormalized pooling partials
    pool_kernel<<<NPOOL, 256>>>(X);
    // 5) deterministic final reduce + normalize
    reduce_out_kernel<<<DOUT, 256>>>(out);
}

// round 4
// speedup vs baseline: 1.0261x; 1.0261x over previous
#include <cuda_runtime.h>
#include <cstdint>

#define NN 8192
#define DIN 256
#define DOUT 32
#define NPOOL 128

// ---------------- scratch (device globals) ----------------
__device__ float    g_support[NN * DOUT];
__device__ float    g_logits[NN * DOUT];
__device__ unsigned g_colmax_bits[DOUT];
__device__ float    g_sumpart[NPOOL * DOUT];
__device__ float    g_part[NPOOL * DOUT * DIN];

// ---------------- packed fp32x2 (FFMA2) helpers ----------------
__device__ __forceinline__ unsigned long long pack2(float x) {
    unsigned long long r;
    asm("mov.b64 %0, {%1, %1};" : "=l"(r) : "f"(x));
    return r;
}
__device__ __forceinline__ unsigned long long ffma2(unsigned long long a,
                                                    unsigned long long b,
                                                    unsigned long long c) {
    unsigned long long d;
    asm("fma.rn.f32x2 %0, %1, %2, %3;" : "=l"(d) : "l"(a), "l"(b), "l"(c));
    return d;
}
__device__ __forceinline__ float2 unpack2(unsigned long long v) {
    float2 f;
    asm("mov.b64 {%0, %1}, %2;" : "=f"(f.x), "=f"(f.y) : "l"(v));
    return f;
}

// monotone float<->uint order-preserving key
__device__ __forceinline__ unsigned fkey(float f) {
    int b = __float_as_int(f);
    return (unsigned)(b ^ ((b >> 31) | 0x80000000));
}
__device__ __forceinline__ float funkey(unsigned u) {
    int b = (u & 0x80000000u) ? (int)(u ^ 0x80000000u) : ~(int)u;
    return __int_as_float(b);
}

// ---------------------------------------------------------------------------
// C[M x 32] = A[M x K] @ S[K x 32]  (round-1 tiling: 64 rows/CTA, 2 rows/lane,
// 8 warps k-split, chunk=32k, inner loop 32 FFMA2 : 10 LDS)
// NEW: launch_bounds(256,2) -> 2 CTAs/SM (194KB smem) -> 4 warps/SMSP.
// Optional epilogue: per-column max via atomicMax on monotone keys
// (order-independent -> deterministic).
// ---------------------------------------------------------------------------
#define ABUF_STRIDE (32 * 65)           // floats per warp
#define SBUF_BASE   (8 * ABUF_STRIDE)
#define GEMM_SMEM_BYTES ((SBUF_BASE + 8 * 32 * 32) * 4)   // 99328 B

__global__ void __launch_bounds__(256, 2)
gemm_n32_kernel(const float* __restrict__ A, const float* __restrict__ S,
                float* __restrict__ C, int K, int do_max, int do_init)
{
    extern __shared__ float smem[];
    __shared__ unsigned smax[DOUT];
    const int t  = threadIdx.x;
    const int w  = t >> 5;
    const int l  = t & 31;
    const int rb = blockIdx.x * 64;

    if (do_init && blockIdx.x == 0 && t < DOUT) g_colmax_bits[t] = 0u;
    if (do_max && t < DOUT) smax[t] = 0u;

    float* a_buf = smem + w * ABUF_STRIDE;
    float* s_buf = smem + SBUF_BASE + w * (32 * 32);

    const int kslice = K >> 3;
    const int nchunk = kslice >> 5;
    const int k0 = w * kslice;

    unsigned long long acc0[16], acc1[16];
#pragma unroll
    for (int i = 0; i < 16; i++) { acc0[i] = 0ull; acc1[i] = 0ull; }

    for (int ch = 0; ch < nchunk; ch++) {
        const int kc = k0 + ch * 32;
        __syncwarp();
        // stage A: 64 rows x 32 k -> transposed [k][row], pad 65 (conflict-free)
#pragma unroll
        for (int j = 0; j < 16; j++) {
            int f   = j * 32 + l;
            int row = f >> 3;
            int k4  = (f & 7) << 2;
            float4 v = *reinterpret_cast<const float4*>(
                A + (size_t)(rb + row) * K + kc + k4);
            a_buf[(k4 + 0) * 65 + row] = v.x;
            a_buf[(k4 + 1) * 65 + row] = v.y;
            a_buf[(k4 + 2) * 65 + row] = v.z;
            a_buf[(k4 + 3) * 65 + row] = v.w;
        }
        // stage S: 32 k x 32 c, contiguous
#pragma unroll
        for (int j = 0; j < 8; j++) {
            int f = j * 32 + l;
            *reinterpret_cast<float4*>(s_buf + f * 4) =
                *reinterpret_cast<const float4*>(S + (size_t)kc * 32 + f * 4);
        }
        __syncwarp();
        // compute: lane owns rows (l, l+32) x all 32 cols
#pragma unroll 4
        for (int k = 0; k < 32; k++) {
            unsigned long long a0 = pack2(a_buf[k * 65 + l]);
            unsigned long long a1 = pack2(a_buf[k * 65 + l + 32]);
            const ulonglong2* s2 =
                reinterpret_cast<const ulonglong2*>(s_buf + k * 32);
#pragma unroll
            for (int c = 0; c < 8; c++) {
                ulonglong2 sv = s2[c];                 // LDS.128 broadcast
                acc0[2 * c]     = ffma2(a0, sv.x, acc0[2 * c]);
                acc0[2 * c + 1] = ffma2(a0, sv.y, acc0[2 * c + 1]);
                acc1[2 * c]     = ffma2(a1, sv.x, acc1[2 * c]);
                acc1[2 * c + 1] = ffma2(a1, sv.y, acc1[2 * c + 1]);
            }
        }
    }

    // ---- cross-warp fixed-order reduce (deterministic) ----
    __syncthreads();
    float* red = smem;  // overlay [8][64][33] = 67584 B
#pragma unroll
    for (int c = 0; c < 16; c++) {
        float2 v0 = unpack2(acc0[c]);
        float2 v1 = unpack2(acc1[c]);
        red[(w * 64 + l) * 33 + 2 * c]          = v0.x;
        red[(w * 64 + l) * 33 + 2 * c + 1]      = v0.y;
        red[(w * 64 + l + 32) * 33 + 2 * c]     = v1.x;
        red[(w * 64 + l + 32) * 33 + 2 * c + 1] = v1.y;
    }
    __syncthreads();
    {
        int row = t >> 2;
        int c0  = (t & 3) * 8;
        float r[8];
#pragma unroll
        for (int i = 0; i < 8; i++) r[i] = 0.0f;
#pragma unroll
        for (int ww = 0; ww < 8; ww++) {
            const float* p = red + (ww * 64 + row) * 33 + c0;
#pragma unroll
            for (int i = 0; i < 8; i++) r[i] += p[i];
        }
        float4* dst = reinterpret_cast<float4*>(C + (size_t)(rb + row) * 32 + c0);
        dst[0] = make_float4(r[0], r[1], r[2], r[3]);
        dst[1] = make_float4(r[4], r[5], r[6], r[7]);
        if (do_max) {
#pragma unroll
            for (int i = 0; i < 8; i++)
                atomicMax(&smax[c0 + i], fkey(r[i]));
        }
    }
    if (do_max) {
        __syncthreads();
        if (t < DOUT) atomicMax(&g_colmax_bits[t], smax[t]);
    }
}

// ---------------------------------------------------------------------------
// Partial exp-sums per 64-row block (coalesced reads, fixed-order reduce)
// ---------------------------------------------------------------------------
__global__ void __launch_bounds__(256, 2)
expsum_kernel()
{
    __shared__ float sred[64 * 33];
    __shared__ float cmax[DOUT];
    const int t  = threadIdx.x;
    const int rb = blockIdx.x * 64;

    if (t < DOUT) cmax[t] = funkey(g_colmax_bits[t]);
    __syncthreads();

    const int row = t >> 2;
    const int c0  = (t & 3) * 8;
#pragma unroll
    for (int h = 0; h < 2; h++) {
        float4 v = *reinterpret_cast<const float4*>(
            g_logits + (size_t)(rb + row) * DOUT + c0 + h * 4);
        sred[row * 33 + c0 + h * 4 + 0] = __expf(v.x - cmax[c0 + h * 4 + 0]);
        sred[row * 33 + c0 + h * 4 + 1] = __expf(v.y - cmax[c0 + h * 4 + 1]);
        sred[row * 33 + c0 + h * 4 + 2] = __expf(v.z - cmax[c0 + h * 4 + 2]);
        sred[row * 33 + c0 + h * 4 + 3] = __expf(v.w - cmax[c0 + h * 4 + 3]);
    }
    __syncthreads();
    if (t < DOUT) {
        float s = 0.f;
#pragma unroll 8
        for (int r = 0; r < 64; r++) s += sred[r * 33 + t];
        g_sumpart[blockIdx.x * DOUT + t] = s;
    }
}

// ---------------------------------------------------------------------------
// UNNORMALIZED pooling partials: part[blk][c][d] = sum_i exp(lg-max) * X[i][d]
// (normalization deferred to reduce_out -> no colinv kernel, no extra dep)
// 128 CTAs x 64 rows; thread t = feature d; row loop unrolled x8 (MLP 8).
// ---------------------------------------------------------------------------
__global__ void __launch_bounds__(256, 2)
pool_kernel(const float* __restrict__ X)
{
    __shared__ float wsm[64 * DOUT];
    __shared__ float cmax[DOUT];
    const int t  = threadIdx.x;
    const int rb = blockIdx.x * 64;

    if (t < DOUT) cmax[t] = funkey(g_colmax_bits[t]);
    __syncthreads();

#pragma unroll
    for (int q = 0; q < 8; q++) {
        int idx = t * 8 + q;
        int il  = idx >> 5;
        int c   = idx & 31;
        float lg = g_logits[(size_t)(rb + il) * DOUT + c];
        wsm[idx] = __expf(lg - cmax[c]);
    }
    __syncthreads();

    unsigned long long acc[16];
#pragma unroll
    for (int i = 0; i < 16; i++) acc[i] = 0ull;

    for (int g = 0; g < 8; g++) {
        float xv[8];
#pragma unroll
        for (int q = 0; q < 8; q++)
            xv[q] = X[(size_t)(rb + g * 8 + q) * DIN + t];   // 8 indep LDGs
#pragma unroll
        for (int q = 0; q < 8; q++) {
            unsigned long long xp = pack2(xv[q]);
            const ulonglong2* wv =
                reinterpret_cast<const ulonglong2*>(wsm + (g * 8 + q) * DOUT);
#pragma unroll
            for (int c = 0; c < 8; c++) {
                ulonglong2 sv = wv[c];
                acc[2 * c]     = ffma2(xp, sv.x, acc[2 * c]);
                acc[2 * c + 1] = ffma2(xp, sv.y, acc[2 * c + 1]);
            }
        }
    }

    float* pp = g_part + (size_t)blockIdx.x * (DOUT * DIN);
#pragma unroll
    for (int c = 0; c < 16; c++) {
        float2 v = unpack2(acc[c]);
        pp[(2 * c) * DIN + t]     = v.x;
        pp[(2 * c + 1) * DIN + t] = v.y;
    }
}

// ---------------------------------------------------------------------------
// Final reduce + normalize: out[c][d] = (1/sum_exp[c]) * sum_b part[b][c][d]
// ---------------------------------------------------------------------------
__global__ void reduce_out_kernel(float* __restrict__ out)
{
    __shared__ float sred[128];
    const int c = blockIdx.x;     // 32
    const int t = threadIdx.x;    // 256

    if (t < 128) sred[t] = g_sumpart[t * DOUT + c];
    __syncthreads();
    for (int s = 64; s > 0; s >>= 1) {
        if (t < s) sred[t] += sred[t + s];
        __syncthreads();
    }
    const float inv = 1.0f / sred[0];

    float s = 0.0f;
#pragma unroll 8
    for (int b = 0; b < NPOOL; b++)
        s += g_part[(size_t)b * (DOUT * DIN) + c * DIN + t];
    out[c * DIN + t] = s * inv;
}

// ---------------------------------------------------------------------------
extern "C" void kernel_launch(void* const* d_in, const int* in_sizes, int n_in,
                              void* d_out, int out_size)
{
    const float* X = (const float*)d_in[0];   // main_feat [8192,256]
    const float* A = (const float*)d_in[1];   // main_adj  [8192,8192]
    const float* W = (const float*)d_in[2];   // W         [256,32]
    // d_in[3] = b: per-column constant -> softmax over axis 0 invariant -> dropped
    float* out = (float*)d_out;

    float *sup, *logits;
    cudaGetSymbolAddress((void**)&sup, g_support);
    cudaGetSymbolAddress((void**)&logits, g_logits);

    cudaFuncSetAttribute(gemm_n32_kernel,
                         cudaFuncAttributeMaxDynamicSharedMemorySize,
                         GEMM_SMEM_BYTES);

    // 1) support = X @ W  (+ zero colmax from CTA 0)
    gemm_n32_kernel<<<NN / 64, 256, GEMM_SMEM_BYTES>>>(X, W, sup, DIN, 0, 1);
    // 2) logits = A @ support  (+ fused per-column max epilogue)
    gemm_n32_kernel<<<NN / 64, 256, GEMM_SMEM_BYTES>>>(A, sup, logits, NN, 1, 0);
    // 3) partial exp-sums
    expsum_kernel<<<NPOOL, 256>>>();
    // 4) unnormalized pooling partials
    pool_kernel<<<NPOOL, 256>>>(X);
    // 5) deterministic final reduce + normalize
    reduce_out_kernel<<<DOUT, 256>>>(out);
}

// round 6
// speedup vs baseline: 1.8053x; 1.7593x over previous
#include <cuda_runtime.h>
#include <cuda_bf16.h>
#include <cstdint>

#define NN 8192
#define DIN 256
#define DOUT 32
#define NPOOL 128
#define NCHUNK 128            // per k-half: 4096 / 32

__device__ __nv_bfloat16 g_Bhi[DOUT * NN];   // support hi, n-major [32][8192]
__device__ __nv_bfloat16 g_Blo[DOUT * NN];   // support lo
__device__ float    g_logits[NN * DOUT];
__device__ unsigned g_colmax_bits[DOUT];
__device__ float    g_sumpart[NPOOL * DOUT];
__device__ float    g_part[NPOOL * DOUT * DIN];

// ---------------- helpers ----------------
__device__ __forceinline__ unsigned long long pack2(float x) {
    unsigned long long r; asm("mov.b64 %0, {%1, %1};" : "=l"(r) : "f"(x)); return r;
}
__device__ __forceinline__ unsigned long long ffma2(unsigned long long a,
                                                    unsigned long long b,
                                                    unsigned long long c) {
    unsigned long long d;
    asm("fma.rn.f32x2 %0, %1, %2, %3;" : "=l"(d) : "l"(a), "l"(b), "l"(c));
    return d;
}
__device__ __forceinline__ float2 unpack2(unsigned long long v) {
    float2 f; asm("mov.b64 {%0, %1}, %2;" : "=f"(f.x), "=f"(f.y) : "l"(v)); return f;
}
__device__ __forceinline__ unsigned fkey(float f) {
    int b = __float_as_int(f);
    return (unsigned)(b ^ ((b >> 31) | 0x80000000));
}
__device__ __forceinline__ float funkey(unsigned u) {
    int b = (u & 0x80000000u) ? (int)(u ^ 0x80000000u) : ~(int)u;
    return __int_as_float(b);
}
__device__ __forceinline__ uint32_t pckb(__nv_bfloat16 a, __nv_bfloat16 b) {
    __nv_bfloat162 h; h.x = a; h.y = b;
    return *reinterpret_cast<uint32_t*>(&h);
}
__device__ __forceinline__ void mma_bf16(float& c0, float& c1, float& c2, float& c3,
                                         uint32_t a0, uint32_t a1, uint32_t a2,
                                         uint32_t a3, uint32_t b0, uint32_t b1) {
    asm volatile(
        "mma.sync.aligned.m16n8k16.row.col.f32.bf16.bf16.f32 "
        "{%0,%1,%2,%3}, {%4,%5,%6,%7}, {%8,%9}, {%0,%1,%2,%3};"
        : "+f"(c0), "+f"(c1), "+f"(c2), "+f"(c3)
        : "r"(a0), "r"(a1), "r"(a2), "r"(a3), "r"(b0), "r"(b1));
}

// ---------------------------------------------------------------------------
// gemm2: logits = A[8192x8192] @ support[8192x32] via mma.sync bf16 3-term.
// 128 CTAs x 64 rows, 8 warps = 4 m16-tiles x 2 K-halves (4096 each).
// SMEM word layout per buffer (uint32 words):
//   A_hi [64r][36]  @0      A_lo @2304
//   B_hi [2h][32n][20] @4608   B_lo @5888      total 7168 words = 28672 B
// ---------------------------------------------------------------------------
#define BUFW 7168
#define ALO_OFF 2304
#define BHI_OFF 4608
#define BLO_OFF 5888
#define GEMM2_SMEM (2 * BUFW * 4)

__device__ __forceinline__ void g2_load(const float* __restrict__ A,
                                        const uint32_t* __restrict__ BHg,
                                        const uint32_t* __restrict__ BLg,
                                        int rb, int ch, int t,
                                        float4 (&pa)[4], uint32_t (&pbh)[4],
                                        uint32_t (&pbl)[4]) {
#pragma unroll
    for (int j = 0; j < 4; j++) {
        int f = t + j * 256;
        int row = f >> 4, q = f & 15, hf = q >> 3, kk = q & 7;
        pa[j] = *reinterpret_cast<const float4*>(
            A + (size_t)(rb + row) * NN + hf * 4096 + ch * 32 + kk * 4);
        int seg = f >> 4, wd = f & 15, hs = seg >> 5, ns = seg & 31;
        int gw = ns * 4096 + hs * 2048 + ch * 16 + wd;
        pbh[j] = BHg[gw];
        pbl[j] = BLg[gw];
    }
}

__device__ __forceinline__ void g2_stage(uint32_t* __restrict__ sb, int t,
                                         const float4 (&pa)[4],
                                         const uint32_t (&pbh)[4],
                                         const uint32_t (&pbl)[4]) {
#pragma unroll
    for (int j = 0; j < 4; j++) {
        int f = t + j * 256;
        int row = f >> 4, q = f & 15, hf = q >> 3, kk = q & 7;
        float4 v = pa[j];
        __nv_bfloat16 hx = __float2bfloat16(v.x), hy = __float2bfloat16(v.y);
        __nv_bfloat16 hz = __float2bfloat16(v.z), hw = __float2bfloat16(v.w);
        uint32_t wh0 = pckb(hx, hy), wh1 = pckb(hz, hw);
        uint32_t wl0 = pckb(__float2bfloat16(v.x - __bfloat162float(hx)),
                            __float2bfloat16(v.y - __bfloat162float(hy)));
        uint32_t wl1 = pckb(__float2bfloat16(v.z - __bfloat162float(hz)),
                            __float2bfloat16(v.w - __bfloat162float(hw)));
        int idx = row * 36 + hf * 16 + kk * 2;
        *reinterpret_cast<uint2*>(sb + idx)           = make_uint2(wh0, wh1);
        *reinterpret_cast<uint2*>(sb + ALO_OFF + idx) = make_uint2(wl0, wl1);
        int seg = f >> 4, wd = f & 15, hs = seg >> 5, ns = seg & 31;
        int bidx = hs * 640 + ns * 20 + wd;
        sb[BHI_OFF + bidx] = pbh[j];
        sb[BLO_OFF + bidx] = pbl[j];
    }
}

__global__ void __launch_bounds__(256, 1)
gemm2_kernel(const float* __restrict__ A)
{
    extern __shared__ uint32_t smu[];
    __shared__ unsigned smax[DOUT];
    const int t = threadIdx.x;
    const int w = t >> 5, lane = t & 31;
    const int gid = lane >> 2, tid4 = lane & 3;
    const int half = w >> 2, m0 = (w & 3) * 16;
    const int rb = blockIdx.x * 64;
    const uint32_t* __restrict__ BHg = (const uint32_t*)g_Bhi;
    const uint32_t* __restrict__ BLg = (const uint32_t*)g_Blo;

    if (t < DOUT) smax[t] = 0u;

    float acc[4][4];
#pragma unroll
    for (int j = 0; j < 4; j++)
#pragma unroll
        for (int i = 0; i < 4; i++) acc[j][i] = 0.0f;

    float4 pa[4]; uint32_t pbh[4], pbl[4];
    g2_load(A, BHg, BLg, rb, 0, t, pa, pbh, pbl);
    g2_stage(smu, t, pa, pbh, pbl);
    __syncthreads();

    for (int ch = 0; ch < NCHUNK; ch++) {
        const uint32_t* sb = smu + (ch & 1) * BUFW;
        if (ch + 1 < NCHUNK)
            g2_load(A, BHg, BLg, rb, ch + 1, t, pa, pbh, pbl);

#pragma unroll
        for (int s = 0; s < 2; s++) {
            const int ab = (m0 + gid) * 36 + half * 16 + s * 8;
            uint32_t ah0 = sb[ab + tid4],           ah1 = sb[ab + 288 + tid4];
            uint32_t ah2 = sb[ab + tid4 + 4],       ah3 = sb[ab + 288 + tid4 + 4];
            uint32_t al0 = sb[ALO_OFF + ab + tid4], al1 = sb[ALO_OFF + ab + 288 + tid4];
            uint32_t al2 = sb[ALO_OFF + ab + tid4 + 4];
            uint32_t al3 = sb[ALO_OFF + ab + 288 + tid4 + 4];
#pragma unroll
            for (int j = 0; j < 4; j++) {
                const int bx = half * 640 + (gid + 8 * j) * 20 + s * 8;
                uint32_t bh0 = sb[BHI_OFF + bx + tid4], bh1 = sb[BHI_OFF + bx + tid4 + 4];
                uint32_t bl0 = sb[BLO_OFF + bx + tid4], bl1 = sb[BLO_OFF + bx + tid4 + 4];
                mma_bf16(acc[j][0], acc[j][1], acc[j][2], acc[j][3],
                         ah0, ah1, ah2, ah3, bh0, bh1);
                mma_bf16(acc[j][0], acc[j][1], acc[j][2], acc[j][3],
                         ah0, ah1, ah2, ah3, bl0, bl1);
                mma_bf16(acc[j][0], acc[j][1], acc[j][2], acc[j][3],
                         al0, al1, al2, al3, bh0, bh1);
            }
        }
        if (ch + 1 < NCHUNK)
            g2_stage(smu + ((ch + 1) & 1) * BUFW, t, pa, pbh, pbl);
        __syncthreads();
    }

    // ---- epilogue: add K-halves (fixed order), write logits, colmax ----
    float* red = (float*)smu;   // [64][33]
    if (half == 1) {
#pragma unroll
        for (int j = 0; j < 4; j++) {
            int r0 = m0 + gid, c = 8 * j + 2 * tid4;
            red[r0 * 33 + c]           = acc[j][0];
            red[r0 * 33 + c + 1]       = acc[j][1];
            red[(r0 + 8) * 33 + c]     = acc[j][2];
            red[(r0 + 8) * 33 + c + 1] = acc[j][3];
        }
    }
    __syncthreads();
    if (half == 0) {
#pragma unroll
        for (int j = 0; j < 4; j++) {
            int r0 = m0 + gid, c = 8 * j + 2 * tid4;
            float v0 = acc[j][0] + red[r0 * 33 + c];
            float v1 = acc[j][1] + red[r0 * 33 + c + 1];
            float v2 = acc[j][2] + red[(r0 + 8) * 33 + c];
            float v3 = acc[j][3] + red[(r0 + 8) * 33 + c + 1];
            *reinterpret_cast<float2*>(&g_logits[(size_t)(rb + r0) * DOUT + c]) =
                make_float2(v0, v1);
            *reinterpret_cast<float2*>(&g_logits[(size_t)(rb + r0 + 8) * DOUT + c]) =
                make_float2(v2, v3);
            atomicMax(&smax[c],     fkey(fmaxf(v0, v2)));
            atomicMax(&smax[c + 1], fkey(fmaxf(v1, v3)));
        }
    }
    __syncthreads();
    if (t < DOUT) atomicMax(&g_colmax_bits[t], smax[t]);
}

// ---------------------------------------------------------------------------
// gemm1: support = X @ W, written pre-split + pre-transposed as bf16 hi/lo.
// Round-1 FFMA2 structure (K=256, single chunk per warp).
// ---------------------------------------------------------------------------
#define ABUF_STRIDE (32 * 65)
#define SBUF_BASE   (8 * ABUF_STRIDE)
#define GEMM1_SMEM  ((SBUF_BASE + 8 * 32 * 32) * 4)

__global__ void __launch_bounds__(256)
gemm1_kernel(const float* __restrict__ A, const float* __restrict__ S)
{
    extern __shared__ float smem[];
    const int t = threadIdx.x, w = t >> 5, l = t & 31;
    const int rb = blockIdx.x * 64;
    const int K = DIN;

    if (blockIdx.x == 0 && t < DOUT) g_colmax_bits[t] = 0u;

    float* a_buf = smem + w * ABUF_STRIDE;
    float* s_buf = smem + SBUF_BASE + w * (32 * 32);
    const int kc = w * 32;

    unsigned long long acc0[16], acc1[16];
#pragma unroll
    for (int i = 0; i < 16; i++) { acc0[i] = 0ull; acc1[i] = 0ull; }

#pragma unroll
    for (int j = 0; j < 16; j++) {
        int f = j * 32 + l, row = f >> 3, k4 = (f & 7) << 2;
        float4 v = *reinterpret_cast<const float4*>(
            A + (size_t)(rb + row) * K + kc + k4);
        a_buf[(k4 + 0) * 65 + row] = v.x;
        a_buf[(k4 + 1) * 65 + row] = v.y;
        a_buf[(k4 + 2) * 65 + row] = v.z;
        a_buf[(k4 + 3) * 65 + row] = v.w;
    }
#pragma unroll
    for (int j = 0; j < 8; j++) {
        int f = j * 32 + l;
        *reinterpret_cast<float4*>(s_buf + f * 4) =
            *reinterpret_cast<const float4*>(S + (size_t)kc * 32 + f * 4);
    }
    __syncwarp();
#pragma unroll 4
    for (int k = 0; k < 32; k++) {
        unsigned long long a0 = pack2(a_buf[k * 65 + l]);
        unsigned long long a1 = pack2(a_buf[k * 65 + l + 32]);
        const ulonglong2* s2 = reinterpret_cast<const ulonglong2*>(s_buf + k * 32);
#pragma unroll
        for (int c = 0; c < 8; c++) {
            ulonglong2 sv = s2[c];
            acc0[2 * c]     = ffma2(a0, sv.x, acc0[2 * c]);
            acc0[2 * c + 1] = ffma2(a0, sv.y, acc0[2 * c + 1]);
            acc1[2 * c]     = ffma2(a1, sv.x, acc1[2 * c]);
            acc1[2 * c + 1] = ffma2(a1, sv.y, acc1[2 * c + 1]);
        }
    }

    __syncthreads();
    float* red = smem;
#pragma unroll
    for (int c = 0; c < 16; c++) {
        float2 v0 = unpack2(acc0[c]);
        float2 v1 = unpack2(acc1[c]);
        red[(w * 64 + l) * 33 + 2 * c]          = v0.x;
        red[(w * 64 + l) * 33 + 2 * c + 1]      = v0.y;
        red[(w * 64 + l + 32) * 33 + 2 * c]     = v1.x;
        red[(w * 64 + l + 32) * 33 + 2 * c + 1] = v1.y;
    }
    __syncthreads();
    {
        int row = t >> 2, c0 = (t & 3) * 8;
        float r[8];
#pragma unroll
        for (int i = 0; i < 8; i++) r[i] = 0.0f;
#pragma unroll
        for (int ww = 0; ww < 8; ww++) {
            const float* p = red + (ww * 64 + row) * 33 + c0;
#pragma unroll
            for (int i = 0; i < 8; i++) r[i] += p[i];
        }
#pragma unroll
        for (int i = 0; i < 8; i++) {
            __nv_bfloat16 hi = __float2bfloat16(r[i]);
            g_Bhi[(size_t)(c0 + i) * NN + rb + row] = hi;
            g_Blo[(size_t)(c0 + i) * NN + rb + row] =
                __float2bfloat16(r[i] - __bfloat162float(hi));
        }
    }
}

// ---------------- expsum partials ------------------------------------------
__global__ void __launch_bounds__(256, 2)
expsum_kernel()
{
    __shared__ float sred[64 * 33];
    __shared__ float cmax[DOUT];
    const int t = threadIdx.x, rb = blockIdx.x * 64;
    if (t < DOUT) cmax[t] = funkey(g_colmax_bits[t]);
    __syncthreads();
    const int row = t >> 2, c0 = (t & 3) * 8;
#pragma unroll
    for (int h = 0; h < 2; h++) {
        float4 v = *reinterpret_cast<const float4*>(
            g_logits + (size_t)(rb + row) * DOUT + c0 + h * 4);
        sred[row * 33 + c0 + h * 4 + 0] = __expf(v.x - cmax[c0 + h * 4 + 0]);
        sred[row * 33 + c0 + h * 4 + 1] = __expf(v.y - cmax[c0 + h * 4 + 1]);
        sred[row * 33 + c0 + h * 4 + 2] = __expf(v.z - cmax[c0 + h * 4 + 2]);
        sred[row * 33 + c0 + h * 4 + 3] = __expf(v.w - cmax[c0 + h * 4 + 3]);
    }
    __syncthreads();
    if (t < DOUT) {
        float s = 0.f;
#pragma unroll 8
        for (int r = 0; r < 64; r++) s += sred[r * 33 + t];
        g_sumpart[blockIdx.x * DOUT + t] = s;
    }
}

// ---------------- pool (unnormalized partials) -----------------------------
__global__ void __launch_bounds__(256, 2)
pool_kernel(const float* __restrict__ X)
{
    __shared__ float wsm[64 * DOUT];
    __shared__ float cmax[DOUT];
    const int t = threadIdx.x, rb = blockIdx.x * 64;
    if (t < DOUT) cmax[t] = funkey(g_colmax_bits[t]);
    __syncthreads();
#pragma unroll
    for (int q = 0; q < 8; q++) {
        int idx = t * 8 + q, il = idx >> 5, c = idx & 31;
        wsm[idx] = __expf(g_logits[(size_t)(rb + il) * DOUT + c] - cmax[c]);
    }
    __syncthreads();

    unsigned long long acc[16];
#pragma unroll
    for (int i = 0; i < 16; i++) acc[i] = 0ull;
    for (int g = 0; g < 8; g++) {
        float xv[8];
#pragma unroll
        for (int q = 0; q < 8; q++)
            xv[q] = X[(size_t)(rb + g * 8 + q) * DIN + t];
#pragma unroll
        for (int q = 0; q < 8; q++) {
            unsigned long long xp = pack2(xv[q]);
            const ulonglong2* wv =
                reinterpret_cast<const ulonglong2*>(wsm + (g * 8 + q) * DOUT);
#pragma unroll
            for (int c = 0; c < 8; c++) {
                ulonglong2 sv = wv[c];
                acc[2 * c]     = ffma2(xp, sv.x, acc[2 * c]);
                acc[2 * c + 1] = ffma2(xp, sv.y, acc[2 * c + 1]);
            }
        }
    }
    float* pp = g_part + (size_t)blockIdx.x * (DOUT * DIN);
#pragma unroll
    for (int c = 0; c < 16; c++) {
        float2 v = unpack2(acc[c]);
        pp[(2 * c) * DIN + t]     = v.x;
        pp[(2 * c + 1) * DIN + t] = v.y;
    }
}

// ---------------- final reduce + normalize ---------------------------------
__global__ void reduce_out_kernel(float* __restrict__ out)
{
    __shared__ float sred[128];
    const int c = blockIdx.x, t = threadIdx.x;
    if (t < 128) sred[t] = g_sumpart[t * DOUT + c];
    __syncthreads();
    for (int s = 64; s > 0; s >>= 1) {
        if (t < s) sred[t] += sred[t + s];
        __syncthreads();
    }
    const float inv = 1.0f / sred[0];
    float s = 0.0f;
#pragma unroll 8
    for (int b = 0; b < NPOOL; b++)
        s += g_part[(size_t)b * (DOUT * DIN) + c * DIN + t];
    out[c * DIN + t] = s * inv;
}

extern "C" void kernel_launch(void* const* d_in, const int* in_sizes, int n_in,
                              void* d_out, int out_size)
{
    const float* X = (const float*)d_in[0];
    const float* A = (const float*)d_in[1];
    const float* W = (const float*)d_in[2];
    // d_in[3] = b: per-column constant -> softmax(axis 0) invariant -> dropped
    float* out = (float*)d_out;

    cudaFuncSetAttribute(gemm1_kernel,
                         cudaFuncAttributeMaxDynamicSharedMemorySize, GEMM1_SMEM);
    cudaFuncSetAttribute(gemm2_kernel,
                         cudaFuncAttributeMaxDynamicSharedMemorySize, GEMM2_SMEM);

    gemm1_kernel<<<NN / 64, 256, GEMM1_SMEM>>>(X, W);
    gemm2_kernel<<<NN / 64, 256, GEMM2_SMEM>>>(A);
    expsum_kernel<<<NPOOL, 256>>>();
    pool_kernel<<<NPOOL, 256>>>(X);
    reduce_out_kernel<<<DOUT, 256>>>(out);
}

// round 7
// speedup vs baseline: 2.5485x; 1.4117x over previous
#include <cuda_runtime.h>
#include <cuda_bf16.h>
#include <cstdint>

#define NN 8192
#define DIN 256
#define DOUT 32
#define NPOOL 128
#define NCHUNK 128            // per k-half: 4096 / 32

__device__ __align__(16) __nv_bfloat16 g_Bhi[DOUT * NN];   // support hi, n-major
__device__ __align__(16) __nv_bfloat16 g_Blo[DOUT * NN];   // support lo
__device__ float    g_logits[NN * DOUT];
__device__ unsigned g_colmax_bits[DOUT];
__device__ float    g_sumpart[NPOOL * DOUT];
__device__ float    g_part[NPOOL * DOUT * DIN];

// ---------------- helpers ----------------
__device__ __forceinline__ unsigned long long pack2(float x) {
    unsigned long long r; asm("mov.b64 %0, {%1, %1};" : "=l"(r) : "f"(x)); return r;
}
__device__ __forceinline__ unsigned long long ffma2(unsigned long long a,
                                                    unsigned long long b,
                                                    unsigned long long c) {
    unsigned long long d;
    asm("fma.rn.f32x2 %0, %1, %2, %3;" : "=l"(d) : "l"(a), "l"(b), "l"(c));
    return d;
}
__device__ __forceinline__ float2 unpack2(unsigned long long v) {
    float2 f; asm("mov.b64 {%0, %1}, %2;" : "=f"(f.x), "=f"(f.y) : "l"(v)); return f;
}
__device__ __forceinline__ unsigned fkey(float f) {
    int b = __float_as_int(f);
    return (unsigned)(b ^ ((b >> 31) | 0x80000000));
}
__device__ __forceinline__ float funkey(unsigned u) {
    int b = (u & 0x80000000u) ? (int)(u ^ 0x80000000u) : ~(int)u;
    return __int_as_float(b);
}
__device__ __forceinline__ uint32_t pckb(__nv_bfloat16 a, __nv_bfloat16 b) {
    __nv_bfloat162 h; h.x = a; h.y = b;
    return *reinterpret_cast<uint32_t*>(&h);
}
__device__ __forceinline__ void split2(float2 v, uint32_t& hi, uint32_t& lo) {
    __nv_bfloat16 hx = __float2bfloat16(v.x), hy = __float2bfloat16(v.y);
    hi = pckb(hx, hy);
    lo = pckb(__float2bfloat16(v.x - __bfloat162float(hx)),
              __float2bfloat16(v.y - __bfloat162float(hy)));
}
__device__ __forceinline__ uint32_t smem_u32(const void* p) {
    uint32_t a;
    asm("{ .reg .u64 t; cvta.to.shared.u64 t, %1; cvt.u32.u64 %0, t; }"
        : "=r"(a) : "l"(p));
    return a;
}
__device__ __forceinline__ void mma_bf16(float& c0, float& c1, float& c2, float& c3,
                                         uint32_t a0, uint32_t a1, uint32_t a2,
                                         uint32_t a3, uint32_t b0, uint32_t b1) {
    asm volatile(
        "mma.sync.aligned.m16n8k16.row.col.f32.bf16.bf16.f32 "
        "{%0,%1,%2,%3}, {%4,%5,%6,%7}, {%8,%9}, {%0,%1,%2,%3};"
        : "+f"(c0), "+f"(c1), "+f"(c2), "+f"(c3)
        : "r"(a0), "r"(a1), "r"(a2), "r"(a3), "r"(b0), "r"(b1));
}
#define CP16(sm, gp) asm volatile( \
    "cp.async.cg.shared.global [%0], [%1], 16;" :: "r"(sm), "l"(gp) : "memory")
#define CP_COMMIT() asm volatile("cp.async.commit_group;" ::: "memory")
#define CP_WAIT2()  asm volatile("cp.async.wait_group 2;" ::: "memory")

// ---------------------------------------------------------------------------
// gemm2: logits = A @ support, mma.sync bf16 3-term, cp.async 4-deep ring.
// 128 CTAs x 64 rows, 8 warps = 4 m16-tiles x 2 K-halves.
// Buffer (uint32 words): A fp32 [half][64r][36] @0 (4608 w)
//                        B_hi [half][32n][20] @4608, B_lo @5888. BUFW=7168.
// ---------------------------------------------------------------------------
#define BUFW 7168
#define BHI_OFF 4608
#define BLO_OFF 5888
#define RING 4
#define GEMM2_SMEM (RING * BUFW * 4)     // 114688 B

__global__ void __launch_bounds__(256, 1)
gemm2_kernel(const float* __restrict__ A)
{
    extern __shared__ uint32_t smu[];
    __shared__ unsigned smax[DOUT];
    const int t = threadIdx.x;
    const int w = t >> 5, lane = t & 31;
    const int gid = lane >> 2, t4 = lane & 3;
    const int half = w >> 2, m0 = (w & 3) * 16;
    const int rb = blockIdx.x * 64;
    const uint32_t* __restrict__ BHg = (const uint32_t*)g_Bhi;
    const uint32_t* __restrict__ BLg = (const uint32_t*)g_Blo;
    const uint32_t smaddr = smem_u32(smu);

    if (t < DOUT) smax[t] = 0u;

    // per-thread cp.async descriptors (A: 4 x 16B, B: 2 x 16B per chunk)
    const float* gA[4]; uint32_t sA[4];
#pragma unroll
    for (int j = 0; j < 4; j++) {
        int f = t + j * 256;
        int hf = f >> 9, r = (f >> 3) & 63, seg = f & 7;
        gA[j] = A + (size_t)(rb + r) * NN + hf * 4096 + seg * 4;
        sA[j] = smaddr + 4u * (hf * 2304 + r * 36 + seg * 4);
    }
    const uint32_t* gB[2]; uint32_t sB[2];
#pragma unroll
    for (int j = 0; j < 2; j++) {
        int f = t + j * 256;
        int arr = f >> 8, rem = f & 255;
        int hs = rem >> 7, ns = (rem >> 2) & 31, sg = rem & 3;
        gB[j] = (arr ? BLg : BHg) + ns * 4096 + hs * 2048 + sg * 4;
        sB[j] = smaddr + 4u * ((arr ? BLO_OFF : BHI_OFF) + hs * 640 + ns * 20 + sg * 4);
    }

    float acc[4][4];
#pragma unroll
    for (int j = 0; j < 4; j++)
#pragma unroll
        for (int i = 0; i < 4; i++) acc[j][i] = 0.0f;

    // prologue: prefetch chunks 0..2
#pragma unroll
    for (int p = 0; p < 3; p++) {
        uint32_t bo = (uint32_t)p * (BUFW * 4);
#pragma unroll
        for (int j = 0; j < 4; j++) CP16(sA[j] + bo, gA[j] + p * 32);
#pragma unroll
        for (int j = 0; j < 2; j++) CP16(sB[j] + bo, gB[j] + p * 16);
        CP_COMMIT();
    }

    for (int ch = 0; ch < NCHUNK; ch++) {
        CP_WAIT2();            // chunk ch resident (this thread's groups)
        __syncthreads();       // all threads' groups + prev compute done
        if (ch + 3 < NCHUNK) { // refill buffer (ch-1)&3 with chunk ch+3
            uint32_t bo = (uint32_t)((ch + 3) & 3) * (BUFW * 4);
            int ko = (ch + 3) * 32, kw = (ch + 3) * 16;
#pragma unroll
            for (int j = 0; j < 4; j++) CP16(sA[j] + bo, gA[j] + ko);
#pragma unroll
            for (int j = 0; j < 2; j++) CP16(sB[j] + bo, gB[j] + kw);
        }
        CP_COMMIT();           // empty group at tail keeps count consistent

        const uint32_t* sb = smu + (ch & 3) * BUFW;
        const float* sbf = (const float*)sb;
#pragma unroll
        for (int s = 0; s < 2; s++) {
            const int ab = half * 2304 + s * 16 + 2 * t4;
            float2 v00 = *reinterpret_cast<const float2*>(sbf + ab + (m0 + gid) * 36);
            float2 v10 = *reinterpret_cast<const float2*>(sbf + ab + (m0 + gid + 8) * 36);
            float2 v01 = *reinterpret_cast<const float2*>(sbf + ab + 8 + (m0 + gid) * 36);
            float2 v11 = *reinterpret_cast<const float2*>(sbf + ab + 8 + (m0 + gid + 8) * 36);
            uint32_t ah0, ah1, ah2, ah3, al0, al1, al2, al3;
            split2(v00, ah0, al0);
            split2(v10, ah1, al1);
            split2(v01, ah2, al2);
            split2(v11, ah3, al3);
#pragma unroll
            for (int j = 0; j < 4; j++) {
                const int bx = BHI_OFF + half * 640 + (gid + 8 * j) * 20 + s * 8 + t4;
                uint32_t bh0 = sb[bx], bh1 = sb[bx + 4];
                uint32_t bl0 = sb[bx + (BLO_OFF - BHI_OFF)];
                uint32_t bl1 = sb[bx + (BLO_OFF - BHI_OFF) + 4];
                mma_bf16(acc[j][0], acc[j][1], acc[j][2], acc[j][3],
                         ah0, ah1, ah2, ah3, bh0, bh1);
                mma_bf16(acc[j][0], acc[j][1], acc[j][2], acc[j][3],
                         ah0, ah1, ah2, ah3, bl0, bl1);
                mma_bf16(acc[j][0], acc[j][1], acc[j][2], acc[j][3],
                         al0, al1, al2, al3, bh0, bh1);
            }
        }
    }
    __syncthreads();

    // ---- epilogue: add K-halves (fixed order), write logits, colmax ----
    float* red = (float*)smu;   // overlay [64][33]
    if (half == 1) {
#pragma unroll
        for (int j = 0; j < 4; j++) {
            int r0 = m0 + gid, c = 8 * j + 2 * t4;
            red[r0 * 33 + c]           = acc[j][0];
            red[r0 * 33 + c + 1]       = acc[j][1];
            red[(r0 + 8) * 33 + c]     = acc[j][2];
            red[(r0 + 8) * 33 + c + 1] = acc[j][3];
        }
    }
    __syncthreads();
    if (half == 0) {
#pragma unroll
        for (int j = 0; j < 4; j++) {
            int r0 = m0 + gid, c = 8 * j + 2 * t4;
            float v0 = acc[j][0] + red[r0 * 33 + c];
            float v1 = acc[j][1] + red[r0 * 33 + c + 1];
            float v2 = acc[j][2] + red[(r0 + 8) * 33 + c];
            float v3 = acc[j][3] + red[(r0 + 8) * 33 + c + 1];
            *reinterpret_cast<float2*>(&g_logits[(size_t)(rb + r0) * DOUT + c]) =
                make_float2(v0, v1);
            *reinterpret_cast<float2*>(&g_logits[(size_t)(rb + r0 + 8) * DOUT + c]) =
                make_float2(v2, v3);
            atomicMax(&smax[c],     fkey(fmaxf(v0, v2)));
            atomicMax(&smax[c + 1], fkey(fmaxf(v1, v3)));
        }
    }
    __syncthreads();
    if (t < DOUT) atomicMax(&g_colmax_bits[t], smax[t]);
}

// ---------------------------------------------------------------------------
// gemm1: support = X @ W, written pre-split + pre-transposed bf16 hi/lo.
// ---------------------------------------------------------------------------
#define ABUF_STRIDE (32 * 65)
#define SBUF_BASE   (8 * ABUF_STRIDE)
#define GEMM1_SMEM  ((SBUF_BASE + 8 * 32 * 32) * 4)

__global__ void __launch_bounds__(256)
gemm1_kernel(const float* __restrict__ A, const float* __restrict__ S)
{
    extern __shared__ float smem[];
    const int t = threadIdx.x, w = t >> 5, l = t & 31;
    const int rb = blockIdx.x * 64;
    const int K = DIN;

    if (blockIdx.x == 0 && t < DOUT) g_colmax_bits[t] = 0u;

    float* a_buf = smem + w * ABUF_STRIDE;
    float* s_buf = smem + SBUF_BASE + w * (32 * 32);
    const int kc = w * 32;

    unsigned long long acc0[16], acc1[16];
#pragma unroll
    for (int i = 0; i < 16; i++) { acc0[i] = 0ull; acc1[i] = 0ull; }

#pragma unroll
    for (int j = 0; j < 16; j++) {
        int f = j * 32 + l, row = f >> 3, k4 = (f & 7) << 2;
        float4 v = *reinterpret_cast<const float4*>(
            A + (size_t)(rb + row) * K + kc + k4);
        a_buf[(k4 + 0) * 65 + row] = v.x;
        a_buf[(k4 + 1) * 65 + row] = v.y;
        a_buf[(k4 + 2) * 65 + row] = v.z;
        a_buf[(k4 + 3) * 65 + row] = v.w;
    }
#pragma unroll
    for (int j = 0; j < 8; j++) {
        int f = j * 32 + l;
        *reinterpret_cast<float4*>(s_buf + f * 4) =
            *reinterpret_cast<const float4*>(S + (size_t)kc * 32 + f * 4);
    }
    __syncwarp();
#pragma unroll 4
    for (int k = 0; k < 32; k++) {
        unsigned long long a0 = pack2(a_buf[k * 65 + l]);
        unsigned long long a1 = pack2(a_buf[k * 65 + l + 32]);
        const ulonglong2* s2 = reinterpret_cast<const ulonglong2*>(s_buf + k * 32);
#pragma unroll
        for (int c = 0; c < 8; c++) {
            ulonglong2 sv = s2[c];
            acc0[2 * c]     = ffma2(a0, sv.x, acc0[2 * c]);
            acc0[2 * c + 1] = ffma2(a0, sv.y, acc0[2 * c + 1]);
            acc1[2 * c]     = ffma2(a1, sv.x, acc1[2 * c]);
            acc1[2 * c + 1] = ffma2(a1, sv.y, acc1[2 * c + 1]);
        }
    }

    __syncthreads();
    float* red = smem;
#pragma unroll
    for (int c = 0; c < 16; c++) {
        float2 v0 = unpack2(acc0[c]);
        float2 v1 = unpack2(acc1[c]);
        red[(w * 64 + l) * 33 + 2 * c]          = v0.x;
        red[(w * 64 + l) * 33 + 2 * c + 1]      = v0.y;
        red[(w * 64 + l + 32) * 33 + 2 * c]     = v1.x;
        red[(w * 64 + l + 32) * 33 + 2 * c + 1] = v1.y;
    }
    __syncthreads();
    {
        int row = t >> 2, c0 = (t & 3) * 8;
        float r[8];
#pragma unroll
        for (int i = 0; i < 8; i++) r[i] = 0.0f;
#pragma unroll
        for (int ww = 0; ww < 8; ww++) {
            const float* p = red + (ww * 64 + row) * 33 + c0;
#pragma unroll
            for (int i = 0; i < 8; i++) r[i] += p[i];
        }
#pragma unroll
        for (int i = 0; i < 8; i++) {
            __nv_bfloat16 hi = __float2bfloat16(r[i]);
            g_Bhi[(size_t)(c0 + i) * NN + rb + row] = hi;
            g_Blo[(size_t)(c0 + i) * NN + rb + row] =
                __float2bfloat16(r[i] - __bfloat162float(hi));
        }
    }
}

// ---------------- expsum partials ------------------------------------------
__global__ void __launch_bounds__(256, 2)
expsum_kernel()
{
    __shared__ float sred[64 * 33];
    __shared__ float cmax[DOUT];
    const int t = threadIdx.x, rb = blockIdx.x * 64;
    if (t < DOUT) cmax[t] = funkey(g_colmax_bits[t]);
    __syncthreads();
    const int row = t >> 2, c0 = (t & 3) * 8;
#pragma unroll
    for (int h = 0; h < 2; h++) {
        float4 v = *reinterpret_cast<const float4*>(
            g_logits + (size_t)(rb + row) * DOUT + c0 + h * 4);
        sred[row * 33 + c0 + h * 4 + 0] = __expf(v.x - cmax[c0 + h * 4 + 0]);
        sred[row * 33 + c0 + h * 4 + 1] = __expf(v.y - cmax[c0 + h * 4 + 1]);
        sred[row * 33 + c0 + h * 4 + 2] = __expf(v.z - cmax[c0 + h * 4 + 2]);
        sred[row * 33 + c0 + h * 4 + 3] = __expf(v.w - cmax[c0 + h * 4 + 3]);
    }
    __syncthreads();
    if (t < DOUT) {
        float s = 0.f;
#pragma unroll 8
        for (int r = 0; r < 64; r++) s += sred[r * 33 + t];
        g_sumpart[blockIdx.x * DOUT + t] = s;
    }
}

// ---------------- pool: d-split (2x parallelism), unnormalized -------------
__global__ void __launch_bounds__(128, 4)
pool_kernel(const float* __restrict__ X)
{
    __shared__ float wsm[64 * DOUT];
    __shared__ float cmax[DOUT];
    const int t   = threadIdx.x;              // 128
    const int blk = (int)blockIdx.x >> 1;
    const int dh  = (int)blockIdx.x & 1;
    const int rb  = blk * 64;
    const int d   = dh * 128 + t;

    if (t < DOUT) cmax[t] = funkey(g_colmax_bits[t]);
    __syncthreads();
#pragma unroll
    for (int q = 0; q < 16; q++) {
        int idx = t * 16 + q, il = idx >> 5, c = idx & 31;
        wsm[idx] = __expf(g_logits[(size_t)(rb + il) * DOUT + c] - cmax[c]);
    }
    __syncthreads();

    unsigned long long acc[16];
#pragma unroll
    for (int i = 0; i < 16; i++) acc[i] = 0ull;
    for (int g = 0; g < 8; g++) {
        float xv[8];
#pragma unroll
        for (int q = 0; q < 8; q++)
            xv[q] = X[(size_t)(rb + g * 8 + q) * DIN + d];
#pragma unroll
        for (int q = 0; q < 8; q++) {
            unsigned long long xp = pack2(xv[q]);
            const ulonglong2* wv =
                reinterpret_cast<const ulonglong2*>(wsm + (g * 8 + q) * DOUT);
#pragma unroll
            for (int c = 0; c < 8; c++) {
                ulonglong2 sv = wv[c];
                acc[2 * c]     = ffma2(xp, sv.x, acc[2 * c]);
                acc[2 * c + 1] = ffma2(xp, sv.y, acc[2 * c + 1]);
            }
        }
    }
    float* pp = g_part + (size_t)blk * (DOUT * DIN);
#pragma unroll
    for (int c = 0; c < 16; c++) {
        float2 v = unpack2(acc[c]);
        pp[(2 * c) * DIN + d]     = v.x;
        pp[(2 * c + 1) * DIN + d] = v.y;
    }
}

// ---------------- final reduce + normalize ---------------------------------
__global__ void reduce_out_kernel(float* __restrict__ out)
{
    __shared__ float sred[128];
    const int c = blockIdx.x, t = threadIdx.x;
    if (t < 128) sred[t] = g_sumpart[t * DOUT + c];
    __syncthreads();
    for (int s = 64; s > 0; s >>= 1) {
        if (t < s) sred[t] += sred[t + s];
        __syncthreads();
    }
    const float inv = 1.0f / sred[0];
    float s = 0.0f;
#pragma unroll 8
    for (int b = 0; b < NPOOL; b++)
        s += g_part[(size_t)b * (DOUT * DIN) + c * DIN + t];
    out[c * DIN + t] = s * inv;
}

extern "C" void kernel_launch(void* const* d_in, const int* in_sizes, int n_in,
                              void* d_out, int out_size)
{
    const float* X = (const float*)d_in[0];
    const float* A = (const float*)d_in[1];
    const float* W = (const float*)d_in[2];
    // d_in[3] = b: per-column constant -> softmax(axis 0) invariant -> dropped
    float* out = (float*)d_out;

    cudaFuncSetAttribute(gemm1_kernel,
                         cudaFuncAttributeMaxDynamicSharedMemorySize, GEMM1_SMEM);
    cudaFuncSetAttribute(gemm2_kernel,
                         cudaFuncAttributeMaxDynamicSharedMemorySize, GEMM2_SMEM);

    gemm1_kernel<<<NN / 64, 256, GEMM1_SMEM>>>(X, W);
    gemm2_kernel<<<NN / 64, 256, GEMM2_SMEM>>>(A);
    expsum_kernel<<<NPOOL, 256>>>();
    pool_kernel<<<NPOOL * 2, 128>>>(X);
    reduce_out_kernel<<<DOUT, 256>>>(out);
}

// round 8
// speedup vs baseline: 2.6806x; 1.0518x over previous
#include <cuda_runtime.h>
#include <cuda_bf16.h>
#include <cstdint>

#define NN 8192
#define DIN 256
#define DOUT 32
#define NPOOL 128
#define NCHUNK 128            // per k-half: 4096 / 32

__device__ __align__(16) __nv_bfloat16 g_Bhi[DOUT * NN];   // support hi, n-major
__device__ __align__(16) __nv_bfloat16 g_Blo[DOUT * NN];   // support lo
__device__ float    g_logits[NN * DOUT];
__device__ unsigned g_colmax_bits[DOUT];
__device__ float    g_sumpart[NPOOL * DOUT];
__device__ float    g_part[NPOOL * DOUT * DIN];

// ---------------- helpers ----------------
__device__ __forceinline__ unsigned long long pack2(float x) {
    unsigned long long r; asm("mov.b64 %0, {%1, %1};" : "=l"(r) : "f"(x)); return r;
}
__device__ __forceinline__ unsigned long long ffma2(unsigned long long a,
                                                    unsigned long long b,
                                                    unsigned long long c) {
    unsigned long long d;
    asm("fma.rn.f32x2 %0, %1, %2, %3;" : "=l"(d) : "l"(a), "l"(b), "l"(c));
    return d;
}
__device__ __forceinline__ float2 unpack2(unsigned long long v) {
    float2 f; asm("mov.b64 {%0, %1}, %2;" : "=f"(f.x), "=f"(f.y) : "l"(v)); return f;
}
__device__ __forceinline__ unsigned fkey(float f) {
    int b = __float_as_int(f);
    return (unsigned)(b ^ ((b >> 31) | 0x80000000));
}
__device__ __forceinline__ float funkey(unsigned u) {
    int b = (u & 0x80000000u) ? (int)(u ^ 0x80000000u) : ~(int)u;
    return __int_as_float(b);
}
__device__ __forceinline__ uint32_t pckb(__nv_bfloat16 a, __nv_bfloat16 b) {
    __nv_bfloat162 h; h.x = a; h.y = b;
    return *reinterpret_cast<uint32_t*>(&h);
}
// truncation split: hi = top16 bits (exact bf16), lo = RN-bf16 of exact residual
__device__ __forceinline__ void split2t(float2 v, uint32_t& hi, uint32_t& lo) {
    uint32_t u0 = __float_as_uint(v.x), u1 = __float_as_uint(v.y);
    asm("prmt.b32 %0, %1, %2, 0x7632;" : "=r"(hi) : "r"(u0), "r"(u1));
    float l0 = v.x - __uint_as_float(u0 & 0xFFFF0000u);
    float l1 = v.y - __uint_as_float(u1 & 0xFFFF0000u);
    asm("cvt.rn.bf16x2.f32 %0, %1, %2;" : "=r"(lo) : "f"(l1), "f"(l0));
}
__device__ __forceinline__ uint32_t smem_u32(const void* p) {
    uint32_t a;
    asm("{ .reg .u64 t; cvta.to.shared.u64 t, %1; cvt.u32.u64 %0, t; }"
        : "=r"(a) : "l"(p));
    return a;
}
__device__ __forceinline__ void mma_bf16(float& c0, float& c1, float& c2, float& c3,
                                         uint32_t a0, uint32_t a1, uint32_t a2,
                                         uint32_t a3, uint32_t b0, uint32_t b1) {
    asm volatile(
        "mma.sync.aligned.m16n8k16.row.col.f32.bf16.bf16.f32 "
        "{%0,%1,%2,%3}, {%4,%5,%6,%7}, {%8,%9}, {%0,%1,%2,%3};"
        : "+f"(c0), "+f"(c1), "+f"(c2), "+f"(c3)
        : "r"(a0), "r"(a1), "r"(a2), "r"(a3), "r"(b0), "r"(b1));
}
#define CP16(sm, gp) asm volatile( \
    "cp.async.cg.shared.global [%0], [%1], 16;" :: "r"(sm), "l"(gp) : "memory")
#define CP_COMMIT() asm volatile("cp.async.commit_group;" ::: "memory")
#define CP_WAIT4()  asm volatile("cp.async.wait_group 4;" ::: "memory")

// ---------------------------------------------------------------------------
// gemm2: logits = A @ support, mma.sync bf16 3-term, cp.async 6-deep ring.
// 128 CTAs x 64 rows, 8 warps = 4 m16-tiles x 2 K-halves.
// Buffer (uint32 words): A fp32 [half][64r][36] @0 (4608 w)
//                        B_hi [half][32n][20] @4608, B_lo @5888. BUFW=7168.
// ---------------------------------------------------------------------------
#define BUFW 7168
#define BHI_OFF 4608
#define BLO_OFF 5888
#define RING 6
#define GEMM2_SMEM (RING * BUFW * 4)     // 172032 B

__global__ void __launch_bounds__(256, 1)
gemm2_kernel(const float* __restrict__ A)
{
    extern __shared__ uint32_t smu[];
    __shared__ unsigned smax[DOUT];
    const int t = threadIdx.x;
    const int w = t >> 5, lane = t & 31;
    const int gid = lane >> 2, t4 = lane & 3;
    const int half = w >> 2, m0 = (w & 3) * 16;
    const int rb = blockIdx.x * 64;
    const uint32_t* __restrict__ BHg = (const uint32_t*)g_Bhi;
    const uint32_t* __restrict__ BLg = (const uint32_t*)g_Blo;
    const uint32_t smaddr = smem_u32(smu);

    if (t < DOUT) smax[t] = 0u;

    // per-thread cp.async descriptors (A: 4 x 16B, B: 2 x 16B per chunk)
    const float* gA[4]; uint32_t sA[4];
#pragma unroll
    for (int j = 0; j < 4; j++) {
        int f = t + j * 256;
        int hf = f >> 9, r = (f >> 3) & 63, seg = f & 7;
        gA[j] = A + (size_t)(rb + r) * NN + hf * 4096 + seg * 4;
        sA[j] = smaddr + 4u * (hf * 2304 + r * 36 + seg * 4);
    }
    const uint32_t* gB[2]; uint32_t sB[2];
#pragma unroll
    for (int j = 0; j < 2; j++) {
        int f = t + j * 256;
        int arr = f >> 8, rem = f & 255;
        int hs = rem >> 7, ns = (rem >> 2) & 31, sg = rem & 3;
        gB[j] = (arr ? BLg : BHg) + ns * 4096 + hs * 2048 + sg * 4;
        sB[j] = smaddr + 4u * ((arr ? BLO_OFF : BHI_OFF) + hs * 640 + ns * 20 + sg * 4);
    }

    float acc[4][4];
#pragma unroll
    for (int j = 0; j < 4; j++)
#pragma unroll
        for (int i = 0; i < 4; i++) acc[j][i] = 0.0f;

    // prologue: prefetch chunks 0..4 into buffers 0..4
#pragma unroll
    for (int p = 0; p < 5; p++) {
        uint32_t bo = (uint32_t)p * (BUFW * 4);
#pragma unroll
        for (int j = 0; j < 4; j++) CP16(sA[j] + bo, gA[j] + p * 32);
#pragma unroll
        for (int j = 0; j < 2; j++) CP16(sB[j] + bo, gB[j] + p * 16);
        CP_COMMIT();
    }

    int bufc = 0, bufp = 5;     // compute buffer, prefetch buffer (mod RING)
    for (int ch = 0; ch < NCHUNK; ch++) {
        CP_WAIT4();            // >=5 groups pending -> wait until chunk ch done
        __syncthreads();       // all threads' chunk-ch groups visible
        if (ch + 5 < NCHUNK) { // refill freed buffer with chunk ch+5
            uint32_t bo = (uint32_t)bufp * (BUFW * 4);
            int ko = (ch + 5) * 32, kw = (ch + 5) * 16;
#pragma unroll
            for (int j = 0; j < 4; j++) CP16(sA[j] + bo, gA[j] + ko);
#pragma unroll
            for (int j = 0; j < 2; j++) CP16(sB[j] + bo, gB[j] + kw);
        }
        CP_COMMIT();           // empty-at-tail keeps group count consistent
        if (++bufp == RING) bufp = 0;

        const uint32_t* sb = smu + bufc * BUFW;
        if (++bufc == RING) bufc = 0;
        const float* sbf = (const float*)sb;
#pragma unroll
        for (int s = 0; s < 2; s++) {
            const int ab = half * 2304 + s * 16 + 2 * t4;
            float2 v00 = *reinterpret_cast<const float2*>(sbf + ab + (m0 + gid) * 36);
            float2 v10 = *reinterpret_cast<const float2*>(sbf + ab + (m0 + gid + 8) * 36);
            float2 v01 = *reinterpret_cast<const float2*>(sbf + ab + 8 + (m0 + gid) * 36);
            float2 v11 = *reinterpret_cast<const float2*>(sbf + ab + 8 + (m0 + gid + 8) * 36);
            uint32_t ah0, ah1, ah2, ah3, al0, al1, al2, al3;
            split2t(v00, ah0, al0);
            split2t(v10, ah1, al1);
            split2t(v01, ah2, al2);
            split2t(v11, ah3, al3);
#pragma unroll
            for (int j = 0; j < 4; j++) {
                const int bx = BHI_OFF + half * 640 + (gid + 8 * j) * 20 + s * 8 + t4;
                uint32_t bh0 = sb[bx], bh1 = sb[bx + 4];
                uint32_t bl0 = sb[bx + (BLO_OFF - BHI_OFF)];
                uint32_t bl1 = sb[bx + (BLO_OFF - BHI_OFF) + 4];
                mma_bf16(acc[j][0], acc[j][1], acc[j][2], acc[j][3],
                         ah0, ah1, ah2, ah3, bh0, bh1);
                mma_bf16(acc[j][0], acc[j][1], acc[j][2], acc[j][3],
                         ah0, ah1, ah2, ah3, bl0, bl1);
                mma_bf16(acc[j][0], acc[j][1], acc[j][2], acc[j][3],
                         al0, al1, al2, al3, bh0, bh1);
            }
        }
    }
    __syncthreads();

    // ---- epilogue: add K-halves (fixed order), write logits, colmax ----
    float* red = (float*)smu;   // overlay [64][33]
    if (half == 1) {
#pragma unroll
        for (int j = 0; j < 4; j++) {
            int r0 = m0 + gid, c = 8 * j + 2 * t4;
            red[r0 * 33 + c]           = acc[j][0];
            red[r0 * 33 + c + 1]       = acc[j][1];
            red[(r0 + 8) * 33 + c]     = acc[j][2];
            red[(r0 + 8) * 33 + c + 1] = acc[j][3];
        }
    }
    __syncthreads();
    if (half == 0) {
#pragma unroll
        for (int j = 0; j < 4; j++) {
            int r0 = m0 + gid, c = 8 * j + 2 * t4;
            float v0 = acc[j][0] + red[r0 * 33 + c];
            float v1 = acc[j][1] + red[r0 * 33 + c + 1];
            float v2 = acc[j][2] + red[(r0 + 8) * 33 + c];
            float v3 = acc[j][3] + red[(r0 + 8) * 33 + c + 1];
            *reinterpret_cast<float2*>(&g_logits[(size_t)(rb + r0) * DOUT + c]) =
                make_float2(v0, v1);
            *reinterpret_cast<float2*>(&g_logits[(size_t)(rb + r0 + 8) * DOUT + c]) =
                make_float2(v2, v3);
            atomicMax(&smax[c],     fkey(fmaxf(v0, v2)));
            atomicMax(&smax[c + 1], fkey(fmaxf(v1, v3)));
        }
    }
    __syncthreads();
    if (t < DOUT) atomicMax(&g_colmax_bits[t], smax[t]);
}

// ---------------------------------------------------------------------------
// gemm1: support = X @ W, written pre-split + pre-transposed bf16 hi/lo.
// (hi = RN here; gemm2's B split stays RN — only A uses truncation split)
// ---------------------------------------------------------------------------
#define ABUF_STRIDE (32 * 65)
#define SBUF_BASE   (8 * ABUF_STRIDE)
#define GEMM1_SMEM  ((SBUF_BASE + 8 * 32 * 32) * 4)

__global__ void __launch_bounds__(256)
gemm1_kernel(const float* __restrict__ A, const float* __restrict__ S)
{
    extern __shared__ float smem[];
    const int t = threadIdx.x, w = t >> 5, l = t & 31;
    const int rb = blockIdx.x * 64;
    const int K = DIN;

    if (blockIdx.x == 0 && t < DOUT) g_colmax_bits[t] = 0u;

    float* a_buf = smem + w * ABUF_STRIDE;
    float* s_buf = smem + SBUF_BASE + w * (32 * 32);
    const int kc = w * 32;

    unsigned long long acc0[16], acc1[16];
#pragma unroll
    for (int i = 0; i < 16; i++) { acc0[i] = 0ull; acc1[i] = 0ull; }

#pragma unroll
    for (int j = 0; j < 16; j++) {
        int f = j * 32 + l, row = f >> 3, k4 = (f & 7) << 2;
        float4 v = *reinterpret_cast<const float4*>(
            A + (size_t)(rb + row) * K + kc + k4);
        a_buf[(k4 + 0) * 65 + row] = v.x;
        a_buf[(k4 + 1) * 65 + row] = v.y;
        a_buf[(k4 + 2) * 65 + row] = v.z;
        a_buf[(k4 + 3) * 65 + row] = v.w;
    }
#pragma unroll
    for (int j = 0; j < 8; j++) {
        int f = j * 32 + l;
        *reinterpret_cast<float4*>(s_buf + f * 4) =
            *reinterpret_cast<const float4*>(S + (size_t)kc * 32 + f * 4);
    }
    __syncwarp();
#pragma unroll 4
    for (int k = 0; k < 32; k++) {
        unsigned long long a0 = pack2(a_buf[k * 65 + l]);
        unsigned long long a1 = pack2(a_buf[k * 65 + l + 32]);
        const ulonglong2* s2 = reinterpret_cast<const ulonglong2*>(s_buf + k * 32);
#pragma unroll
        for (int c = 0; c < 8; c++) {
            ulonglong2 sv = s2[c];
            acc0[2 * c]     = ffma2(a0, sv.x, acc0[2 * c]);
            acc0[2 * c + 1] = ffma2(a0, sv.y, acc0[2 * c + 1]);
            acc1[2 * c]     = ffma2(a1, sv.x, acc1[2 * c]);
            acc1[2 * c + 1] = ffma2(a1, sv.y, acc1[2 * c + 1]);
        }
    }

    __syncthreads();
    float* red = smem;
#pragma unroll
    for (int c = 0; c < 16; c++) {
        float2 v0 = unpack2(acc0[c]);
        float2 v1 = unpack2(acc1[c]);
        red[(w * 64 + l) * 33 + 2 * c]          = v0.x;
        red[(w * 64 + l) * 33 + 2 * c + 1]      = v0.y;
        red[(w * 64 + l + 32) * 33 + 2 * c]     = v1.x;
        red[(w * 64 + l + 32) * 33 + 2 * c + 1] = v1.y;
    }
    __syncthreads();
    {
        int row = t >> 2, c0 = (t & 3) * 8;
        float r[8];
#pragma unroll
        for (int i = 0; i < 8; i++) r[i] = 0.0f;
#pragma unroll
        for (int ww = 0; ww < 8; ww++) {
            const float* p = red + (ww * 64 + row) * 33 + c0;
#pragma unroll
            for (int i = 0; i < 8; i++) r[i] += p[i];
        }
#pragma unroll
        for (int i = 0; i < 8; i++) {
            __nv_bfloat16 hi = __float2bfloat16(r[i]);
            g_Bhi[(size_t)(c0 + i) * NN + rb + row] = hi;
            g_Blo[(size_t)(c0 + i) * NN + rb + row] =
                __float2bfloat16(r[i] - __bfloat162float(hi));
        }
    }
}

// ---------------- expsum partials ------------------------------------------
__global__ void __launch_bounds__(256, 2)
expsum_kernel()
{
    __shared__ float sred[64 * 33];
    __shared__ float cmax[DOUT];
    const int t = threadIdx.x, rb = blockIdx.x * 64;
    if (t < DOUT) cmax[t] = funkey(g_colmax_bits[t]);
    __syncthreads();
    const int row = t >> 2, c0 = (t & 3) * 8;
#pragma unroll
    for (int h = 0; h < 2; h++) {
        float4 v = *reinterpret_cast<const float4*>(
            g_logits + (size_t)(rb + row) * DOUT + c0 + h * 4);
        sred[row * 33 + c0 + h * 4 + 0] = __expf(v.x - cmax[c0 + h * 4 + 0]);
        sred[row * 33 + c0 + h * 4 + 1] = __expf(v.y - cmax[c0 + h * 4 + 1]);
        sred[row * 33 + c0 + h * 4 + 2] = __expf(v.z - cmax[c0 + h * 4 + 2]);
        sred[row * 33 + c0 + h * 4 + 3] = __expf(v.w - cmax[c0 + h * 4 + 3]);
    }
    __syncthreads();
    if (t < DOUT) {
        float s = 0.f;
#pragma unroll 8
        for (int r = 0; r < 64; r++) s += sred[r * 33 + t];
        g_sumpart[blockIdx.x * DOUT + t] = s;
    }
}

// ---------------- pool: d-split (2x parallelism), unnormalized -------------
__global__ void __launch_bounds__(128, 4)
pool_kernel(const float* __restrict__ X)
{
    __shared__ float wsm[64 * DOUT];
    __shared__ float cmax[DOUT];
    const int t   = threadIdx.x;              // 128
    const int blk = (int)blockIdx.x >> 1;
    const int dh  = (int)blockIdx.x & 1;
    const int rb  = blk * 64;
    const int d   = dh * 128 + t;

    if (t < DOUT) cmax[t] = funkey(g_colmax_bits[t]);
    __syncthreads();
#pragma unroll
    for (int q = 0; q < 16; q++) {
        int idx = t * 16 + q, il = idx >> 5, c = idx & 31;
        wsm[idx] = __expf(g_logits[(size_t)(rb + il) * DOUT + c] - cmax[c]);
    }
    __syncthreads();

    unsigned long long acc[16];
#pragma unroll
    for (int i = 0; i < 16; i++) acc[i] = 0ull;
    for (int g = 0; g < 8; g++) {
        float xv[8];
#pragma unroll
        for (int q = 0; q < 8; q++)
            xv[q] = X[(size_t)(rb + g * 8 + q) * DIN + d];
#pragma unroll
        for (int q = 0; q < 8; q++) {
            unsigned long long xp = pack2(xv[q]);
            const ulonglong2* wv =
                reinterpret_cast<const ulonglong2*>(wsm + (g * 8 + q) * DOUT);
#pragma unroll
            for (int c = 0; c < 8; c++) {
                ulonglong2 sv = wv[c];
                acc[2 * c]     = ffma2(xp, sv.x, acc[2 * c]);
                acc[2 * c + 1] = ffma2(xp, sv.y, acc[2 * c + 1]);
            }
        }
    }
    float* pp = g_part + (size_t)blk * (DOUT * DIN);
#pragma unroll
    for (int c = 0; c < 16; c++) {
        float2 v = unpack2(acc[c]);
        pp[(2 * c) * DIN + d]     = v.x;
        pp[(2 * c + 1) * DIN + d] = v.y;
    }
}

// ---------------- final reduce + normalize ---------------------------------
__global__ void reduce_out_kernel(float* __restrict__ out)
{
    __shared__ float sred[128];
    const int c = blockIdx.x, t = threadIdx.x;
    if (t < 128) sred[t] = g_sumpart[t * DOUT + c];
    __syncthreads();
    for (int s = 64; s > 0; s >>= 1) {
        if (t < s) sred[t] += sred[t + s];
        __syncthreads();
    }
    const float inv = 1.0f / sred[0];
    float s = 0.0f;
#pragma unroll 8
    for (int b = 0; b < NPOOL; b++)
        s += g_part[(size_t)b * (DOUT * DIN) + c * DIN + t];
    out[c * DIN + t] = s * inv;
}

extern "C" void kernel_launch(void* const* d_in, const int* in_sizes, int n_in,
                              void* d_out, int out_size)
{
    const float* X = (const float*)d_in[0];
    const float* A = (const float*)d_in[1];
    const float* W = (const float*)d_in[2];
    // d_in[3] = b: per-column constant -> softmax(axis 0) invariant -> dropped
    float* out = (float*)d_out;

    cudaFuncSetAttribute(gemm1_kernel,
                         cudaFuncAttributeMaxDynamicSharedMemorySize, GEMM1_SMEM);
    cudaFuncSetAttribute(gemm2_kernel,
                         cudaFuncAttributeMaxDynamicSharedMemorySize, GEMM2_SMEM);

    gemm1_kernel<<<NN / 64, 256, GEMM1_SMEM>>>(X, W);
    gemm2_kernel<<<NN / 64, 256, GEMM2_SMEM>>>(A);
    expsum_kernel<<<NPOOL, 256>>>();
    pool_kernel<<<NPOOL * 2, 128>>>(X);
    reduce_out_kernel<<<DOUT, 256>>>(out);
}